// round 10
// baseline (speedup 1.0000x reference)
#include <cuda_runtime.h>
#include <cuda_bf16.h>
#include <math.h>
#include <stdint.h>

#define FULL 0xFFFFFFFFu

static constexpr int B_      = 2;
static constexpr int LQ_     = 13294;
static constexpr int LEN_IN_ = 13294;
static constexpr int DM_     = 256;
static constexpr int M_ROWS  = B_ * LQ_;      // 26588
static constexpr int MT_     = 208;           // M tiles of 128
static constexpr int M_PAD   = MT_ * 128;     // 26624

// ---------------- scratch (static device globals; allocation-free) ----------
__device__ __align__(128) __nv_bfloat16 g_Acat1[M_PAD * 512];  // bf16(inflat) hi|lo
__device__ __align__(128) __nv_bfloat16 g_Acat2[M_PAD * 512];  // bf16(query)  hi|lo
__device__ __align__(128) __nv_bfloat16 g_Acat3[M_PAD * 512];  // bf16(sampled) hi|lo
__device__ __align__(128) __nv_bfloat16 g_Bval[256 * 512];     // B[n,k] hi|lo
__device__ __align__(128) __nv_bfloat16 g_Bqkv[384 * 512];
__device__ __align__(128) __nv_bfloat16 g_Bout[256 * 512];
__device__ float g_bcat[384];
__device__ __align__(16) float g_value[M_ROWS * 256];  // fp32 value (sampler input)
__device__ float g_proj [M_ROWS * 384];       // fp32 [off(256) | logits(128)]

__constant__ float c_WH[4] = {100.f, 50.f, 25.f, 13.f};
__constant__ int   c_Wi[4] = {100, 50, 25, 13};
__constant__ int   c_S [4] = {0, 10000, 12500, 13125};

// ---------------- helpers ---------------------------------------------------
__device__ __forceinline__ void split_bf16(float x, __nv_bfloat16& h, __nv_bfloat16& l) {
    h = __float2bfloat16(x);
    l = __float2bfloat16(x - __bfloat162float(h));
}
__device__ __forceinline__ uint32_t smem_u32(const void* p) {
    uint32_t a;
    asm("{ .reg .u64 t; cvta.to.shared.u64 t, %1; cvt.u32.u64 %0, t; }" : "=r"(a) : "l"(p));
    return a;
}
__device__ __forceinline__ void ldsm4(uint32_t* r, uint32_t a) {
    asm volatile("ldmatrix.sync.aligned.m8n8.x4.shared.b16 {%0,%1,%2,%3}, [%4];"
                 : "=r"(r[0]), "=r"(r[1]), "=r"(r[2]), "=r"(r[3]) : "r"(a));
}
__device__ __forceinline__ void mma16816(float* d, const uint32_t* a,
                                         uint32_t b0, uint32_t b1) {
    asm volatile(
        "mma.sync.aligned.m16n8k16.row.col.f32.bf16.bf16.f32 "
        "{%0,%1,%2,%3}, {%4,%5,%6,%7}, {%8,%9}, {%0,%1,%2,%3};"
        : "+f"(d[0]), "+f"(d[1]), "+f"(d[2]), "+f"(d[3])
        : "r"(a[0]), "r"(a[1]), "r"(a[2]), "r"(a[3]), "r"(b0), "r"(b1));
}
__device__ __forceinline__ void cp16(uint32_t dst, const void* src) {
    asm volatile("cp.async.cg.shared.global [%0], [%1], 16;" :: "r"(dst), "l"(src));
}
__device__ __forceinline__ void cp_commit() {
    asm volatile("cp.async.commit_group;" ::: "memory");
}
template<int N> __device__ __forceinline__ void cp_wait() {
    asm volatile("cp.async.wait_group %0;" :: "n"(N) : "memory");
}

// ---------------------------------------------------------------------------
// Pack weights: B[n, 0:256]=bf16_hi(W[k,n]), B[n, 256:512]=bf16_lo. Plus the
// concatenated bias and zero-fill of the A_cat pad rows.
// ---------------------------------------------------------------------------
__global__ void pack_misc(const float* __restrict__ Woff,  const float* __restrict__ boff,
                          const float* __restrict__ Wattn, const float* __restrict__ battn,
                          const float* __restrict__ Wval,  const float* __restrict__ Wout)
{
    const int i = blockIdx.x * blockDim.x + threadIdx.x;
    const int which = blockIdx.y;
    if (which == 0) {
        if (i < 256 * 512) {
            int n = i >> 9, kk = i & 511, k = kk & 255;
            float w = Wval[k * 256 + n];
            __nv_bfloat16 h, l; split_bf16(w, h, l);
            g_Bval[i] = (kk < 256) ? h : l;
        }
    } else if (which == 1) {
        if (i < 384 * 512) {
            int n = i >> 9, kk = i & 511, k = kk & 255;
            float w = (n < 256) ? Woff[k * 256 + n] : Wattn[k * 128 + (n - 256)];
            __nv_bfloat16 h, l; split_bf16(w, h, l);
            g_Bqkv[i] = (kk < 256) ? h : l;
        }
    } else if (which == 2) {
        if (i < 256 * 512) {
            int n = i >> 9, kk = i & 511, k = kk & 255;
            float w = Wout[k * 256 + n];
            __nv_bfloat16 h, l; split_bf16(w, h, l);
            g_Bout[i] = (kk < 256) ? h : l;
        }
    } else {
        if (i < 384) g_bcat[i] = (i < 256) ? boff[i] : battn[i - 256];
        int j = i - 384;
        const int PADE = (M_PAD - M_ROWS) * 512;   // 36*512
        if (j >= 0 && j < 3 * PADE) {
            int arr = j / PADE, off = j % PADE;
            __nv_bfloat16 z = __float2bfloat16(0.f);
            __nv_bfloat16* dst = (arr == 0) ? g_Acat1 : (arr == 1) ? g_Acat2 : g_Acat3;
            dst[M_ROWS * 512 + off] = z;
        }
    }
}

// ---------------------------------------------------------------------------
// fp32 [M,256] -> bf16 split [M,512] for inflat (y=0) and query (y=1).
// ---------------------------------------------------------------------------
__global__ void convert_split(const float* __restrict__ inflat,
                              const float* __restrict__ query)
{
    const int e4 = blockIdx.x * blockDim.x + threadIdx.x;
    if (e4 >= M_ROWS * 64) return;
    const float* src = blockIdx.y ? query : inflat;
    __nv_bfloat16* dst = blockIdx.y ? g_Acat2 : g_Acat1;
    const int row = e4 >> 6;
    const int c4  = (e4 & 63) << 2;
    float4 v = *(const float4*)(src + (size_t)row * 256 + c4);
    __nv_bfloat16 h0, l0, h1, l1, h2, l2, h3, l3;
    split_bf16(v.x, h0, l0); split_bf16(v.y, h1, l1);
    split_bf16(v.z, h2, l2); split_bf16(v.w, h3, l3);
    __nv_bfloat162* dh = (__nv_bfloat162*)(dst + (size_t)row * 512 + c4);
    dh[0] = __halves2bfloat162(h0, h1);
    dh[1] = __halves2bfloat162(h2, h3);
    __nv_bfloat162* dl = (__nv_bfloat162*)(dst + (size_t)row * 512 + 256 + c4);
    dl[0] = __halves2bfloat162(l0, l1);
    dl[1] = __halves2bfloat162(l2, l3);
}

// ---------------------------------------------------------------------------
// bf16 split GEMM via mma.sync + cp.async 3-stage pipeline. One CTA = 128x128
// tile, 256 threads = 8 warps (2x4), warp tile 64x32. 12 K-chunks of 64
// (3 segments: Ahi*Bhi, Alo*Bhi, Ahi*Blo), fp32 acc. 2 CTAs/SM.
// Single barrier per chunk: the stage overwritten by issue(cc+2) was last
// read by mma(cc-1), which all warps finished before this chunk's barrier.
// ---------------------------------------------------------------------------
__global__ __launch_bounds__(256, 2)
void gemm_bf16_mma(const __nv_bfloat16* __restrict__ A,
                   const __nv_bfloat16* __restrict__ Bm,
                   const float* __restrict__ bias,
                   float* __restrict__ C, int M, int N, int split,
                   const __nv_bfloat16* __restrict__ A2,
                   const __nv_bfloat16* __restrict__ B2,
                   const float* __restrict__ bias2,
                   float* __restrict__ C2, int N2)
{
    extern __shared__ char dyn[];     // 3 x (16KB A + 16KB B)
    const int tid  = threadIdx.x;
    const int wid  = tid >> 5;
    const int lane = tid & 31;
    const int warp_m = wid & 1;
    const int warp_n = wid >> 1;

    int bx = blockIdx.x;
    if (bx >= split) { A = A2; Bm = B2; bias = bias2; C = C2; N = N2; bx -= split; }
    const int row0 = blockIdx.y * 128;
    const int n0   = bx * 128;

    const uint32_t sbase = smem_u32(dyn);

    float acc[4][4][4];
#pragma unroll
    for (int i = 0; i < 4; i++)
#pragma unroll
        for (int j = 0; j < 4; j++)
#pragma unroll
            for (int k = 0; k < 4; k++) acc[i][j][k] = 0.f;

    const uint4* baseA4 = (const uint4*)(A + (size_t)row0 * 512);
    const uint4* baseB4 = (const uint4*)(Bm + (size_t)n0 * 512);

    const int cr = tid >> 3, ccol = tid & 7;

    auto issue_chunk = [&](int cc) {
        const int s    = cc - (cc / 3) * 3;   // cc % 3
        const int seg  = cc >> 2;
        const int kk   = (cc & 3) * 64;
        const int aoff = (seg == 1) ? 256 : 0;
        const int boff = (seg == 2) ? 256 : 0;
        const uint4* sA = baseA4 + ((aoff + kk) >> 3);
        const uint4* sB = baseB4 + ((boff + kk) >> 3);
        const uint32_t smA = sbase + s * 32768;
        const uint32_t smB = smA + 16384;
#pragma unroll
        for (int i = 0; i < 4; i++) {
            const int r = cr + i * 32;
            const uint32_t off = r * 128 + ccol * 16;
            const uint32_t sw  = off ^ ((off >> 3) & 0x70);
            cp16(smA + sw, sA + (size_t)r * 64 + ccol);
            cp16(smB + sw, sB + (size_t)r * 64 + ccol);
        }
        cp_commit();
    };

    // ldmatrix per-lane constants
    const int t  = lane >> 3;
    const int l7 = lane & 7;
    const uint32_t tlo = (t & 1) * 8;
    const uint32_t tc  = (uint32_t)(t >> 1);
    const uint32_t aRowBase = (warp_m * 64 + tlo + l7) * 128;
    const uint32_t bRowBase = (warp_n * 32 + tlo + l7) * 128;

    auto mma_chunk = [&](int s) {
        const uint32_t baseA = sbase + s * 32768;
        const uint32_t baseB = baseA + 16384;
#pragma unroll
        for (int ks = 0; ks < 4; ks++) {
            const uint32_t csw = (uint32_t)(((ks * 2 + tc) ^ l7) << 4);
            uint32_t bf[2][4];
#pragma unroll
            for (int nt = 0; nt < 2; nt++)
                ldsm4(bf[nt], baseB + bRowBase + nt * (16 * 128) + csw);
#pragma unroll
            for (int mt = 0; mt < 4; mt++) {
                uint32_t af[4];
                ldsm4(af, baseA + aRowBase + mt * (16 * 128) + csw);
                mma16816(acc[mt][0], af, bf[0][0], bf[0][2]);
                mma16816(acc[mt][1], af, bf[0][1], bf[0][3]);
                mma16816(acc[mt][2], af, bf[1][0], bf[1][2]);
                mma16816(acc[mt][3], af, bf[1][1], bf[1][3]);
            }
        }
    };

    // 3-stage pipeline over 12 chunks, one barrier per chunk
    issue_chunk(0);
    issue_chunk(1);
    for (int cc = 0; cc < 12; cc++) {
        if (cc < 11) cp_wait<1>(); else cp_wait<0>();
        __syncthreads();
        if (cc + 2 < 12) issue_chunk(cc + 2);
        mma_chunk(cc - (cc / 3) * 3);
    }

    // epilogue: fragment -> global with bias
#pragma unroll
    for (int mt = 0; mt < 4; mt++) {
        const int m = row0 + warp_m * 64 + mt * 16 + (lane >> 2);
#pragma unroll
        for (int n8 = 0; n8 < 4; n8++) {
            const int c = n0 + warp_n * 32 + n8 * 8 + (lane & 3) * 2;
            const float bx2 = __ldg(&bias[c]);
            const float by2 = __ldg(&bias[c + 1]);
            if (m < M) {
                float2 o = make_float2(acc[mt][n8][0] + bx2, acc[mt][n8][1] + by2);
                *(float2*)(C + (size_t)m * N + c) = o;
            }
            if (m + 8 < M) {
                float2 o = make_float2(acc[mt][n8][2] + bx2, acc[mt][n8][3] + by2);
                *(float2*)(C + (size_t)(m + 8) * N + c) = o;
            }
        }
    }
}

// ---------------------------------------------------------------------------
// Deformable sampling with half-warp corner pairing.
// Phase 1: 128 threads -> per-(head,point) TWO smem entries (one per x-corner
//          side): {offA(y0 row), offB(y1 row), wA, wB}, validity pre-masked.
// Phase 2: warp h; lanes 0-15 handle x0 corners, 16-31 handle x1; each lane
//          owns channels (2j, 2j+1) via float2 loads -> LDG count halved.
//          Final shfl_xor(16) combines halves; hi/lo bf16 written per half.
// ---------------------------------------------------------------------------
__global__ __launch_bounds__(256)
void msda_sample(const float* __restrict__ refp,   // [B, LQ, 4, 2]
                 const float* __restrict__ proj,   // [M, 384]
                 const float* __restrict__ value,  // [B, LEN_IN, 8, 32]
                 __nv_bfloat16* __restrict__ acat) // [M_PAD, 512]
{
    __shared__ float4 sPair[256];   // [(hd*16+p)*2 + half]

    const int bq = blockIdx.x;
    const int tt = threadIdx.x;
    const int b  = bq / LQ_;

    if (tt < 128) {
        const int hd  = tt >> 4;
        const int p   = tt & 15;
        const int lvl = p >> 2;
        const int pp  = p & 3;

        float a = proj[bq * 384 + 256 + hd * 16 + p];
        float m = a;
#pragma unroll
        for (int o = 8; o; o >>= 1) m = fmaxf(m, __shfl_xor_sync(FULL, m, o));
        float e = __expf(a - m);
        float s = e;
#pragma unroll
        for (int o = 8; o; o >>= 1) s += __shfl_xor_sync(FULL, s, o);
        const float w = e / s;

        const float wh = c_WH[lvl];
        const int   Wl = c_Wi[lvl];
        const int   Sl = c_S[lvl];
        const float ox = proj[bq * 384 + hd * 32 + lvl * 8 + pp * 2 + 0];
        const float oy = proj[bq * 384 + hd * 32 + lvl * 8 + pp * 2 + 1];
        const float rx = refp[(bq * 4 + lvl) * 2 + 0];
        const float ry = refp[(bq * 4 + lvl) * 2 + 1];

        const float x = fmaf(rx, wh, ox) - 0.5f;
        const float y = fmaf(ry, wh, oy) - 0.5f;

        const float fx0 = floorf(x), fy0 = floorf(y);
        const int   x0  = (int)fx0,  y0  = (int)fy0;
        const float tx_ = x - fx0,   ty_ = y - fy0;

        const bool vx0 = (x0 >= 0)     && (x0 < Wl);
        const bool vx1 = (x0 + 1 >= 0) && (x0 + 1 < Wl);
        const bool vy0 = (y0 >= 0)     && (y0 < Wl);
        const bool vy1 = (y0 + 1 >= 0) && (y0 + 1 < Wl);

        const int cx0 = min(max(x0, 0),     Wl - 1);
        const int cx1 = min(max(x0 + 1, 0), Wl - 1);
        const int cy0 = min(max(y0, 0),     Wl - 1);
        const int cy1 = min(max(y0 + 1, 0), Wl - 1);

        const float w00 = (vx0 && vy0) ? (1.f - tx_) * (1.f - ty_) * w : 0.f;
        const float w01 = (vx1 && vy0) ? tx_ * (1.f - ty_) * w : 0.f;
        const float w10 = (vx0 && vy1) ? (1.f - tx_) * ty_ * w : 0.f;
        const float w11 = (vx1 && vy1) ? tx_ * ty_ * w : 0.f;

        const int base = b * LEN_IN_ * DM_ + hd * 32;
        const int o00 = base + (Sl + cy0 * Wl + cx0) * DM_;
        const int o01 = base + (Sl + cy0 * Wl + cx1) * DM_;
        const int o10 = base + (Sl + cy1 * Wl + cx0) * DM_;
        const int o11 = base + (Sl + cy1 * Wl + cx1) * DM_;

        // half 0 (lanes 0-15): x0 corners (y0 row, y1 row)
        sPair[tt * 2 + 0] = make_float4(__int_as_float(o00), __int_as_float(o10), w00, w10);
        // half 1 (lanes 16-31): x1 corners
        sPair[tt * 2 + 1] = make_float4(__int_as_float(o01), __int_as_float(o11), w01, w11);
    }
    __syncthreads();

    const int hd   = tt >> 5;
    const int lane = tt & 31;
    const int half = lane >> 4;
    const int j    = lane & 15;
    const float* __restrict__ vp = value + 2 * j;

    float accx = 0.f, accy = 0.f;
#pragma unroll
    for (int p = 0; p < 16; p++) {
        const float4 e = sPair[(hd * 16 + p) * 2 + half];
        const float2 vA = *(const float2*)(vp + __float_as_int(e.x));
        const float2 vB = *(const float2*)(vp + __float_as_int(e.y));
        accx = fmaf(e.z, vA.x, accx);
        accx = fmaf(e.w, vB.x, accx);
        accy = fmaf(e.z, vA.y, accy);
        accy = fmaf(e.w, vB.y, accy);
    }

    // combine the two half-warps (x0 side + x1 side)
    accx += __shfl_xor_sync(FULL, accx, 16);
    accy += __shfl_xor_sync(FULL, accy, 16);

    const __nv_bfloat16 hx = __float2bfloat16(accx);
    const __nv_bfloat16 hy = __float2bfloat16(accy);
    if (half == 0) {
        *(__nv_bfloat162*)(acat + (size_t)bq * 512 + hd * 32 + 2 * j) =
            __halves2bfloat162(hx, hy);
    } else {
        const __nv_bfloat16 lx = __float2bfloat16(accx - __bfloat162float(hx));
        const __nv_bfloat16 ly = __float2bfloat16(accy - __bfloat162float(hy));
        *(__nv_bfloat162*)(acat + (size_t)bq * 512 + 256 + hd * 32 + 2 * j) =
            __halves2bfloat162(lx, ly);
    }
}

// ---------------------------------------------------------------------------
extern "C" void kernel_launch(void* const* d_in, const int* in_sizes, int n_in,
                              void* d_out, int out_size)
{
    const float* query  = (const float*)d_in[0];
    const float* refp   = (const float*)d_in[1];
    const float* inflat = (const float*)d_in[2];
    const float* W_off  = (const float*)d_in[5];
    const float* b_off  = (const float*)d_in[6];
    const float* W_attn = (const float*)d_in[7];
    const float* b_attn = (const float*)d_in[8];
    const float* W_val  = (const float*)d_in[9];
    const float* b_val  = (const float*)d_in[10];
    const float* W_out  = (const float*)d_in[11];
    const float* b_out  = (const float*)d_in[12];
    float* out = (float*)d_out;

    void *pA1, *pA2, *pA3, *pBval, *pBqkv, *pBout, *pbcat, *pvalue, *pproj;
    cudaGetSymbolAddress(&pA1, g_Acat1);
    cudaGetSymbolAddress(&pA2, g_Acat2);
    cudaGetSymbolAddress(&pA3, g_Acat3);
    cudaGetSymbolAddress(&pBval, g_Bval);
    cudaGetSymbolAddress(&pBqkv, g_Bqkv);
    cudaGetSymbolAddress(&pBout, g_Bout);
    cudaGetSymbolAddress(&pbcat, g_bcat);
    cudaGetSymbolAddress(&pvalue, g_value);
    cudaGetSymbolAddress(&pproj, g_proj);

    const int DSMEM = 3 * 32768;   // 96KB
    cudaFuncSetAttribute(gemm_bf16_mma,
                         cudaFuncAttributeMaxDynamicSharedMemorySize, DSMEM);

    pack_misc<<<dim3(768, 4), 256>>>(W_off, b_off, W_attn, b_attn, W_val, W_out);

    convert_split<<<dim3((M_ROWS * 64 + 255) / 256, 2), 256>>>(inflat, query);

    // fused launch: blocks x<2 -> value GEMM (A1*Bval), x>=2 -> proj GEMM (A2*Bqkv)
    gemm_bf16_mma<<<dim3(5, MT_), 256, DSMEM>>>(
        (const __nv_bfloat16*)pA1, (const __nv_bfloat16*)pBval,
        b_val, (float*)pvalue, M_ROWS, 256, 2,
        (const __nv_bfloat16*)pA2, (const __nv_bfloat16*)pBqkv,
        (const float*)pbcat, (float*)pproj, 384);

    msda_sample<<<M_ROWS, 256>>>(refp, (const float*)pproj,
                                 (const float*)pvalue, (__nv_bfloat16*)pA3);

    gemm_bf16_mma<<<dim3(2, MT_), 256, DSMEM>>>(
        (const __nv_bfloat16*)pA3, (const __nv_bfloat16*)pBout,
        b_out, out, M_ROWS, 256, 2,
        (const __nv_bfloat16*)pA3, (const __nv_bfloat16*)pBout,
        b_out, out, 256);
}

// round 13
// speedup vs baseline: 1.4276x; 1.4276x over previous
#include <cuda_runtime.h>
#include <cuda_bf16.h>
#include <cuda_fp16.h>
#include <math.h>
#include <stdint.h>

#define FULL 0xFFFFFFFFu

static constexpr int B_      = 2;
static constexpr int LQ_     = 13294;
static constexpr int LEN_IN_ = 13294;
static constexpr int DM_     = 256;
static constexpr int M_ROWS  = B_ * LQ_;      // 26588
static constexpr int MT_     = 208;           // M tiles of 128
static constexpr int M_PAD   = MT_ * 128;     // 26624

// ---------------- scratch (static device globals; allocation-free) ----------
__device__ __align__(128) __nv_bfloat16 g_Acat1[M_PAD * 512];  // bf16(inflat) hi|lo
__device__ __align__(128) __nv_bfloat16 g_Acat2[M_PAD * 512];  // bf16(query)  hi|lo
__device__ __align__(128) __nv_bfloat16 g_Acat3[M_PAD * 512];  // bf16(sampled) hi|lo
__device__ __align__(128) __nv_bfloat16 g_Bval[256 * 512];     // B[n,k] hi|lo
__device__ __align__(128) __nv_bfloat16 g_Bqkv[384 * 512];
__device__ __align__(128) __nv_bfloat16 g_Bout[256 * 512];
__device__ float g_bcat[384];
__device__ __align__(128) __half g_value16[M_ROWS * 256 + 64]; // fp16 value [b,pos,h,32]
__device__ float g_proj [M_ROWS * 384];       // fp32 [off(256) | logits(128)]

__constant__ float c_WH[4] = {100.f, 50.f, 25.f, 13.f};
__constant__ int   c_Wi[4] = {100, 50, 25, 13};
__constant__ int   c_S [4] = {0, 10000, 12500, 13125};

// ---------------- helpers ---------------------------------------------------
__device__ __forceinline__ void split_bf16(float x, __nv_bfloat16& h, __nv_bfloat16& l) {
    h = __float2bfloat16(x);
    l = __float2bfloat16(x - __bfloat162float(h));
}
__device__ __forceinline__ uint32_t smem_u32(const void* p) {
    uint32_t a;
    asm("{ .reg .u64 t; cvta.to.shared.u64 t, %1; cvt.u32.u64 %0, t; }" : "=r"(a) : "l"(p));
    return a;
}
__device__ __forceinline__ void ldsm4(uint32_t* r, uint32_t a) {
    asm volatile("ldmatrix.sync.aligned.m8n8.x4.shared.b16 {%0,%1,%2,%3}, [%4];"
                 : "=r"(r[0]), "=r"(r[1]), "=r"(r[2]), "=r"(r[3]) : "r"(a));
}
__device__ __forceinline__ void mma16816(float* d, const uint32_t* a,
                                         uint32_t b0, uint32_t b1) {
    asm volatile(
        "mma.sync.aligned.m16n8k16.row.col.f32.bf16.bf16.f32 "
        "{%0,%1,%2,%3}, {%4,%5,%6,%7}, {%8,%9}, {%0,%1,%2,%3};"
        : "+f"(d[0]), "+f"(d[1]), "+f"(d[2]), "+f"(d[3])
        : "r"(a[0]), "r"(a[1]), "r"(a[2]), "r"(a[3]), "r"(b0), "r"(b1));
}
__device__ __forceinline__ void cp16(uint32_t dst, const void* src) {
    asm volatile("cp.async.cg.shared.global [%0], [%1], 16;" :: "r"(dst), "l"(src));
}
__device__ __forceinline__ void cp_commit() {
    asm volatile("cp.async.commit_group;" ::: "memory");
}
template<int N> __device__ __forceinline__ void cp_wait() {
    asm volatile("cp.async.wait_group %0;" :: "n"(N) : "memory");
}

// ---------------------------------------------------------------------------
// Pack weights: B[n, 0:256]=bf16_hi(W[k,n]), B[n, 256:512]=bf16_lo. Plus the
// concatenated bias and zero-fill of the A_cat pad rows.
// ---------------------------------------------------------------------------
__global__ void pack_misc(const float* __restrict__ Woff,  const float* __restrict__ boff,
                          const float* __restrict__ Wattn, const float* __restrict__ battn,
                          const float* __restrict__ Wval,  const float* __restrict__ Wout)
{
    const int i = blockIdx.x * blockDim.x + threadIdx.x;
    const int which = blockIdx.y;
    if (which == 0) {
        if (i < 256 * 512) {
            int n = i >> 9, kk = i & 511, k = kk & 255;
            float w = Wval[k * 256 + n];
            __nv_bfloat16 h, l; split_bf16(w, h, l);
            g_Bval[i] = (kk < 256) ? h : l;
        }
    } else if (which == 1) {
        if (i < 384 * 512) {
            int n = i >> 9, kk = i & 511, k = kk & 255;
            float w = (n < 256) ? Woff[k * 256 + n] : Wattn[k * 128 + (n - 256)];
            __nv_bfloat16 h, l; split_bf16(w, h, l);
            g_Bqkv[i] = (kk < 256) ? h : l;
        }
    } else if (which == 2) {
        if (i < 256 * 512) {
            int n = i >> 9, kk = i & 511, k = kk & 255;
            float w = Wout[k * 256 + n];
            __nv_bfloat16 h, l; split_bf16(w, h, l);
            g_Bout[i] = (kk < 256) ? h : l;
        }
    } else {
        if (i < 384) g_bcat[i] = (i < 256) ? boff[i] : battn[i - 256];
        int j = i - 384;
        const int PADE = (M_PAD - M_ROWS) * 512;   // 36*512
        if (j >= 0 && j < 3 * PADE) {
            int arr = j / PADE, off = j % PADE;
            __nv_bfloat16 z = __float2bfloat16(0.f);
            __nv_bfloat16* dst = (arr == 0) ? g_Acat1 : (arr == 1) ? g_Acat2 : g_Acat3;
            dst[M_ROWS * 512 + off] = z;
        }
    }
}

// ---------------------------------------------------------------------------
// fp32 [M,256] -> bf16 split [M,512] for inflat (y=0) and query (y=1).
// ---------------------------------------------------------------------------
__global__ void convert_split(const float* __restrict__ inflat,
                              const float* __restrict__ query)
{
    const int e4 = blockIdx.x * blockDim.x + threadIdx.x;
    if (e4 >= M_ROWS * 64) return;
    const float* src = blockIdx.y ? query : inflat;
    __nv_bfloat16* dst = blockIdx.y ? g_Acat2 : g_Acat1;
    const int row = e4 >> 6;
    const int c4  = (e4 & 63) << 2;
    float4 v = *(const float4*)(src + (size_t)row * 256 + c4);
    __nv_bfloat16 h0, l0, h1, l1, h2, l2, h3, l3;
    split_bf16(v.x, h0, l0); split_bf16(v.y, h1, l1);
    split_bf16(v.z, h2, l2); split_bf16(v.w, h3, l3);
    __nv_bfloat162* dh = (__nv_bfloat162*)(dst + (size_t)row * 512 + c4);
    dh[0] = __halves2bfloat162(h0, h1);
    dh[1] = __halves2bfloat162(h2, h3);
    __nv_bfloat162* dl = (__nv_bfloat162*)(dst + (size_t)row * 512 + 256 + c4);
    dl[0] = __halves2bfloat162(l0, l1);
    dl[1] = __halves2bfloat162(l2, l3);
}

// ---------------------------------------------------------------------------
// bf16 split GEMM via mma.sync + cp.async 3-stage pipeline (R8 known-good
// two-barrier loop). One CTA = 128x128 tile, 256 threads = 8 warps (2x4),
// warp tile 64x32. 12 K-chunks of 64 (Ahi*Bhi, Alo*Bhi, Ahi*Blo), fp32 acc.
// 2 CTAs/SM. Dual-problem via split. Optional fp16 output (C16 != null).
// ---------------------------------------------------------------------------
__global__ __launch_bounds__(256, 2)
void gemm_bf16_mma(const __nv_bfloat16* __restrict__ A,
                   const __nv_bfloat16* __restrict__ Bm,
                   const float* __restrict__ bias,
                   float* __restrict__ C, __half* __restrict__ C16,
                   int M, int N, int split,
                   const __nv_bfloat16* __restrict__ A2,
                   const __nv_bfloat16* __restrict__ B2,
                   const float* __restrict__ bias2,
                   float* __restrict__ C2, int N2)
{
    extern __shared__ char dyn[];     // 3 x (16KB A + 16KB B)
    const int tid  = threadIdx.x;
    const int wid  = tid >> 5;
    const int lane = tid & 31;
    const int warp_m = wid & 1;
    const int warp_n = wid >> 1;

    int bx = blockIdx.x;
    if (bx >= split) { A = A2; Bm = B2; bias = bias2; C = C2; C16 = nullptr; N = N2; bx -= split; }
    const int row0 = blockIdx.y * 128;
    const int n0   = bx * 128;

    const uint32_t sbase = smem_u32(dyn);

    float acc[4][4][4];
#pragma unroll
    for (int i = 0; i < 4; i++)
#pragma unroll
        for (int j = 0; j < 4; j++)
#pragma unroll
            for (int k = 0; k < 4; k++) acc[i][j][k] = 0.f;

    const uint4* baseA4 = (const uint4*)(A + (size_t)row0 * 512);
    const uint4* baseB4 = (const uint4*)(Bm + (size_t)n0 * 512);

    const int cr = tid >> 3, ccol = tid & 7;

    auto issue_chunk = [&](int cc) {
        const int s    = cc - (cc / 3) * 3;   // cc % 3
        const int seg  = cc >> 2;
        const int kk   = (cc & 3) * 64;
        const int aoff = (seg == 1) ? 256 : 0;
        const int boff = (seg == 2) ? 256 : 0;
        const uint4* sA = baseA4 + ((aoff + kk) >> 3);
        const uint4* sB = baseB4 + ((boff + kk) >> 3);
        const uint32_t smA = sbase + s * 32768;
        const uint32_t smB = smA + 16384;
#pragma unroll
        for (int i = 0; i < 4; i++) {
            const int r = cr + i * 32;
            const uint32_t off = r * 128 + ccol * 16;
            const uint32_t sw  = off ^ ((off >> 3) & 0x70);
            cp16(smA + sw, sA + (size_t)r * 64 + ccol);
            cp16(smB + sw, sB + (size_t)r * 64 + ccol);
        }
        cp_commit();
    };

    // ldmatrix per-lane constants
    const int t  = lane >> 3;
    const int l7 = lane & 7;
    const uint32_t tlo = (t & 1) * 8;
    const uint32_t tc  = (uint32_t)(t >> 1);
    const uint32_t aRowBase = (warp_m * 64 + tlo + l7) * 128;
    const uint32_t bRowBase = (warp_n * 32 + tlo + l7) * 128;

    auto mma_chunk = [&](int s) {
        const uint32_t baseA = sbase + s * 32768;
        const uint32_t baseB = baseA + 16384;
#pragma unroll
        for (int ks = 0; ks < 4; ks++) {
            const uint32_t csw = (uint32_t)(((ks * 2 + tc) ^ l7) << 4);
            uint32_t bf[2][4];
#pragma unroll
            for (int nt = 0; nt < 2; nt++)
                ldsm4(bf[nt], baseB + bRowBase + nt * (16 * 128) + csw);
#pragma unroll
            for (int mt = 0; mt < 4; mt++) {
                uint32_t af[4];
                ldsm4(af, baseA + aRowBase + mt * (16 * 128) + csw);
                mma16816(acc[mt][0], af, bf[0][0], bf[0][2]);
                mma16816(acc[mt][1], af, bf[0][1], bf[0][3]);
                mma16816(acc[mt][2], af, bf[1][0], bf[1][2]);
                mma16816(acc[mt][3], af, bf[1][1], bf[1][3]);
            }
        }
    };

    // 3-stage pipeline over 12 chunks (two barriers per chunk — known-good)
    issue_chunk(0);
    issue_chunk(1);
    int sidx = 0;
    for (int cc = 0; cc < 12; cc++) {
        if (cc < 11) cp_wait<1>(); else cp_wait<0>();
        __syncthreads();
        mma_chunk(sidx);
        __syncthreads();
        if (cc + 2 < 12) issue_chunk(cc + 2);
        sidx = (sidx == 2) ? 0 : sidx + 1;
    }

    // epilogue: fragment -> global with bias (fp32 or fp16)
#pragma unroll
    for (int mt = 0; mt < 4; mt++) {
        const int m = row0 + warp_m * 64 + mt * 16 + (lane >> 2);
#pragma unroll
        for (int n8 = 0; n8 < 4; n8++) {
            const int c = n0 + warp_n * 32 + n8 * 8 + (lane & 3) * 2;
            const float bx2 = __ldg(&bias[c]);
            const float by2 = __ldg(&bias[c + 1]);
            if (C16) {
                if (m < M)
                    *(__half2*)(C16 + (size_t)m * N + c) =
                        __floats2half2_rn(acc[mt][n8][0] + bx2, acc[mt][n8][1] + by2);
                if (m + 8 < M)
                    *(__half2*)(C16 + (size_t)(m + 8) * N + c) =
                        __floats2half2_rn(acc[mt][n8][2] + bx2, acc[mt][n8][3] + by2);
            } else {
                if (m < M) {
                    float2 o = make_float2(acc[mt][n8][0] + bx2, acc[mt][n8][1] + by2);
                    *(float2*)(C + (size_t)m * N + c) = o;
                }
                if (m + 8 < M) {
                    float2 o = make_float2(acc[mt][n8][2] + bx2, acc[mt][n8][3] + by2);
                    *(float2*)(C + (size_t)(m + 8) * N + c) = o;
                }
            }
        }
    }
}

// ---------------------------------------------------------------------------
// Deformable sampling over fp16 value with y-paired half-warp gathers.
// Phase 1 (R8 schema): 128 threads -> per-(head,point) int4 offsets
//          {o00,o10,o01,o11} + float4 weights {w00,w10,w01,w11} (masked).
// Phase 2: warp = head; lane j = channel pair (2j, 2j+1); half 0 (lanes 0-15)
//          accumulates the y0 rows, half 1 the y1 rows. One LDG.32 warp-wide
//          covers BOTH y-rows of a corner column -> 2 gather instr per point
//          (vs 4 with fp32). shfl_xor(16) combines halves; hi/lo bf16 out.
// ---------------------------------------------------------------------------
__global__ __launch_bounds__(256)
void msda_sample(const float* __restrict__ refp,   // [B, LQ, 4, 2]
                 const float* __restrict__ proj,   // [M, 384]
                 const __half* __restrict__ value, // [B, LEN_IN, 8, 32] fp16
                 __nv_bfloat16* __restrict__ acat) // [M_PAD, 512]
{
    __shared__ float4 sW[128];
    __shared__ int4   sO[128];

    const int bq = blockIdx.x;
    const int tt = threadIdx.x;
    const int b  = bq / LQ_;

    if (tt < 128) {
        const int hd  = tt >> 4;
        const int p   = tt & 15;
        const int lvl = p >> 2;
        const int pp  = p & 3;

        float a = proj[bq * 384 + 256 + hd * 16 + p];
        float m = a;
#pragma unroll
        for (int o = 8; o; o >>= 1) m = fmaxf(m, __shfl_xor_sync(FULL, m, o));
        float e = __expf(a - m);
        float s = e;
#pragma unroll
        for (int o = 8; o; o >>= 1) s += __shfl_xor_sync(FULL, s, o);
        const float w = e / s;

        const float wh = c_WH[lvl];
        const int   Wl = c_Wi[lvl];
        const int   Sl = c_S[lvl];
        const float ox = proj[bq * 384 + hd * 32 + lvl * 8 + pp * 2 + 0];
        const float oy = proj[bq * 384 + hd * 32 + lvl * 8 + pp * 2 + 1];
        const float rx = refp[(bq * 4 + lvl) * 2 + 0];
        const float ry = refp[(bq * 4 + lvl) * 2 + 1];

        const float x = fmaf(rx, wh, ox) - 0.5f;
        const float y = fmaf(ry, wh, oy) - 0.5f;

        const float fx0 = floorf(x), fy0 = floorf(y);
        const int   x0  = (int)fx0,  y0  = (int)fy0;
        const float tx_ = x - fx0,   ty_ = y - fy0;

        const bool vx0 = (x0 >= 0)     && (x0 < Wl);
        const bool vx1 = (x0 + 1 >= 0) && (x0 + 1 < Wl);
        const bool vy0 = (y0 >= 0)     && (y0 < Wl);
        const bool vy1 = (y0 + 1 >= 0) && (y0 + 1 < Wl);

        const int cx0 = min(max(x0, 0),     Wl - 1);
        const int cx1 = min(max(x0 + 1, 0), Wl - 1);
        const int cy0 = min(max(y0, 0),     Wl - 1);
        const int cy1 = min(max(y0 + 1, 0), Wl - 1);

        const float w00 = (vx0 && vy0) ? (1.f - tx_) * (1.f - ty_) * w : 0.f;
        const float w01 = (vx1 && vy0) ? tx_ * (1.f - ty_) * w : 0.f;
        const float w10 = (vx0 && vy1) ? (1.f - tx_) * ty_ * w : 0.f;
        const float w11 = (vx1 && vy1) ? tx_ * ty_ * w : 0.f;

        // fp16 element offsets: ((b*LEN_IN + pos)*8 + hd)*32
        const int base = (b * LEN_IN_ + Sl) * 256 + hd * 32;
        int4 ov;
        ov.x = base + (cy0 * Wl + cx0) * 256;   // (y0, x0)
        ov.y = base + (cy1 * Wl + cx0) * 256;   // (y1, x0)
        ov.z = base + (cy0 * Wl + cx1) * 256;   // (y0, x1)
        ov.w = base + (cy1 * Wl + cx1) * 256;   // (y1, x1)

        sO[tt] = ov;
        sW[tt] = make_float4(w00, w10, w01, w11);
    }
    __syncthreads();

    const int hd   = tt >> 5;
    const int lane = tt & 31;
    const int half = lane >> 4;
    const int j    = lane & 15;
    const __half* __restrict__ vp = value + 2 * j;

    float accx = 0.f, accy = 0.f;
#pragma unroll
    for (int p = 0; p < 16; p++) {
        const int4   ov = sO[hd * 16 + p];
        const float4 wv = sW[hd * 16 + p];
        // half 0 -> y0 row (ov.x / ov.z, weights wv.x / wv.z)
        // half 1 -> y1 row (ov.y / ov.w, weights wv.y / wv.w)
        const int   oA = half ? ov.y : ov.x;   // x0 column
        const int   oB = half ? ov.w : ov.z;   // x1 column
        const float wA = half ? wv.y : wv.x;
        const float wB = half ? wv.w : wv.z;
        const __half2 hA = *(const __half2*)(vp + oA);
        const __half2 hB = *(const __half2*)(vp + oB);
        const float2 vA = __half22float2(hA);
        const float2 vB = __half22float2(hB);
        accx = fmaf(wA, vA.x, fmaf(wB, vB.x, accx));
        accy = fmaf(wA, vA.y, fmaf(wB, vB.y, accy));
    }

    // combine y0 + y1 halves
    accx += __shfl_xor_sync(FULL, accx, 16);
    accy += __shfl_xor_sync(FULL, accy, 16);

    const __nv_bfloat16 hx = __float2bfloat16(accx);
    const __nv_bfloat16 hy = __float2bfloat16(accy);
    if (half == 0) {
        *(__nv_bfloat162*)(acat + (size_t)bq * 512 + hd * 32 + 2 * j) =
            __halves2bfloat162(hx, hy);
    } else {
        const __nv_bfloat16 lx = __float2bfloat16(accx - __bfloat162float(hx));
        const __nv_bfloat16 ly = __float2bfloat16(accy - __bfloat162float(hy));
        *(__nv_bfloat162*)(acat + (size_t)bq * 512 + 256 + hd * 32 + 2 * j) =
            __halves2bfloat162(lx, ly);
    }
}

// ---------------------------------------------------------------------------
extern "C" void kernel_launch(void* const* d_in, const int* in_sizes, int n_in,
                              void* d_out, int out_size)
{
    const float* query  = (const float*)d_in[0];
    const float* refp   = (const float*)d_in[1];
    const float* inflat = (const float*)d_in[2];
    const float* W_off  = (const float*)d_in[5];
    const float* b_off  = (const float*)d_in[6];
    const float* W_attn = (const float*)d_in[7];
    const float* b_attn = (const float*)d_in[8];
    const float* W_val  = (const float*)d_in[9];
    const float* b_val  = (const float*)d_in[10];
    const float* W_out  = (const float*)d_in[11];
    const float* b_out  = (const float*)d_in[12];
    float* out = (float*)d_out;

    void *pA1, *pA2, *pA3, *pBval, *pBqkv, *pBout, *pbcat, *pv16, *pproj;
    cudaGetSymbolAddress(&pA1, g_Acat1);
    cudaGetSymbolAddress(&pA2, g_Acat2);
    cudaGetSymbolAddress(&pA3, g_Acat3);
    cudaGetSymbolAddress(&pBval, g_Bval);
    cudaGetSymbolAddress(&pBqkv, g_Bqkv);
    cudaGetSymbolAddress(&pBout, g_Bout);
    cudaGetSymbolAddress(&pbcat, g_bcat);
    cudaGetSymbolAddress(&pv16, g_value16);
    cudaGetSymbolAddress(&pproj, g_proj);

    const int DSMEM = 3 * 32768;   // 96KB
    cudaFuncSetAttribute(gemm_bf16_mma,
                         cudaFuncAttributeMaxDynamicSharedMemorySize, DSMEM);

    pack_misc<<<dim3(768, 4), 256>>>(W_off, b_off, W_attn, b_attn, W_val, W_out);

    convert_split<<<dim3((M_ROWS * 64 + 255) / 256, 2), 256>>>(inflat, query);

    // fused launch: x<2 -> value GEMM (fp16 out), x>=2 -> proj GEMM (fp32 out)
    gemm_bf16_mma<<<dim3(5, MT_), 256, DSMEM>>>(
        (const __nv_bfloat16*)pA1, (const __nv_bfloat16*)pBval,
        b_val, nullptr, (__half*)pv16, M_ROWS, 256, 2,
        (const __nv_bfloat16*)pA2, (const __nv_bfloat16*)pBqkv,
        (const float*)pbcat, (float*)pproj, 384);

    msda_sample<<<M_ROWS, 256>>>(refp, (const float*)pproj,
                                 (const __half*)pv16, (__nv_bfloat16*)pA3);

    gemm_bf16_mma<<<dim3(2, MT_), 256, DSMEM>>>(
        (const __nv_bfloat16*)pA3, (const __nv_bfloat16*)pBout,
        b_out, out, nullptr, M_ROWS, 256, 2,
        (const __nv_bfloat16*)pA3, (const __nv_bfloat16*)pBout,
        b_out, out, 256);
}

// round 14
// speedup vs baseline: 1.5137x; 1.0603x over previous
#include <cuda_runtime.h>
#include <cuda_bf16.h>
#include <cuda_fp16.h>
#include <math.h>
#include <stdint.h>

#define FULL 0xFFFFFFFFu

static constexpr int B_      = 2;
static constexpr int LQ_     = 13294;
static constexpr int LEN_IN_ = 13294;
static constexpr int DM_     = 256;
static constexpr int M_ROWS  = B_ * LQ_;      // 26588
static constexpr int MT_     = 208;           // M tiles of 128
static constexpr int M_PAD   = MT_ * 128;     // 26624

// ---------------- scratch (static device globals; allocation-free) ----------
__device__ __align__(128) __nv_bfloat16 g_Acat1[M_PAD * 512];  // bf16(inflat) hi|lo
__device__ __align__(128) __nv_bfloat16 g_Acat2[M_PAD * 512];  // bf16(query)  hi|lo
__device__ __align__(128) __nv_bfloat16 g_Acat3[M_PAD * 512];  // bf16(sampled) hi|lo
__device__ __align__(128) __nv_bfloat16 g_Bval[256 * 512];     // B[n,k] hi|lo
__device__ __align__(128) __nv_bfloat16 g_Bqkv[384 * 512];
__device__ __align__(128) __nv_bfloat16 g_Bout[256 * 512];
__device__ float g_bcat[384];
__device__ __align__(128) __half g_value16[M_ROWS * 256 + 64]; // fp16 value [b,pos,h,32]
__device__ float g_proj [M_ROWS * 384];       // fp32 [off(256) | logits(128)]

__constant__ float c_WH[4] = {100.f, 50.f, 25.f, 13.f};
__constant__ int   c_Wi[4] = {100, 50, 25, 13};
__constant__ int   c_S [4] = {0, 10000, 12500, 13125};

// ---------------- helpers ---------------------------------------------------
__device__ __forceinline__ void split_bf16(float x, __nv_bfloat16& h, __nv_bfloat16& l) {
    h = __float2bfloat16(x);
    l = __float2bfloat16(x - __bfloat162float(h));
}
__device__ __forceinline__ uint32_t smem_u32(const void* p) {
    uint32_t a;
    asm("{ .reg .u64 t; cvta.to.shared.u64 t, %1; cvt.u32.u64 %0, t; }" : "=r"(a) : "l"(p));
    return a;
}
__device__ __forceinline__ void ldsm4(uint32_t* r, uint32_t a) {
    asm volatile("ldmatrix.sync.aligned.m8n8.x4.shared.b16 {%0,%1,%2,%3}, [%4];"
                 : "=r"(r[0]), "=r"(r[1]), "=r"(r[2]), "=r"(r[3]) : "r"(a));
}
__device__ __forceinline__ void mma16816(float* d, const uint32_t* a,
                                         uint32_t b0, uint32_t b1) {
    asm volatile(
        "mma.sync.aligned.m16n8k16.row.col.f32.bf16.bf16.f32 "
        "{%0,%1,%2,%3}, {%4,%5,%6,%7}, {%8,%9}, {%0,%1,%2,%3};"
        : "+f"(d[0]), "+f"(d[1]), "+f"(d[2]), "+f"(d[3])
        : "r"(a[0]), "r"(a[1]), "r"(a[2]), "r"(a[3]), "r"(b0), "r"(b1));
}
__device__ __forceinline__ void cp16(uint32_t dst, const void* src) {
    asm volatile("cp.async.cg.shared.global [%0], [%1], 16;" :: "r"(dst), "l"(src));
}
__device__ __forceinline__ void cp_commit() {
    asm volatile("cp.async.commit_group;" ::: "memory");
}
template<int N> __device__ __forceinline__ void cp_wait() {
    asm volatile("cp.async.wait_group %0;" :: "n"(N) : "memory");
}

// ---------------------------------------------------------------------------
// Pack weights: B[n, 0:256]=bf16_hi(W[k,n]), B[n, 256:512]=bf16_lo. Plus the
// concatenated bias and zero-fill of the A_cat pad rows.
// ---------------------------------------------------------------------------
__global__ void pack_misc(const float* __restrict__ Woff,  const float* __restrict__ boff,
                          const float* __restrict__ Wattn, const float* __restrict__ battn,
                          const float* __restrict__ Wval,  const float* __restrict__ Wout)
{
    const int i = blockIdx.x * blockDim.x + threadIdx.x;
    const int which = blockIdx.y;
    if (which == 0) {
        if (i < 256 * 512) {
            int n = i >> 9, kk = i & 511, k = kk & 255;
            float w = Wval[k * 256 + n];
            __nv_bfloat16 h, l; split_bf16(w, h, l);
            g_Bval[i] = (kk < 256) ? h : l;
        }
    } else if (which == 1) {
        if (i < 384 * 512) {
            int n = i >> 9, kk = i & 511, k = kk & 255;
            float w = (n < 256) ? Woff[k * 256 + n] : Wattn[k * 128 + (n - 256)];
            __nv_bfloat16 h, l; split_bf16(w, h, l);
            g_Bqkv[i] = (kk < 256) ? h : l;
        }
    } else if (which == 2) {
        if (i < 256 * 512) {
            int n = i >> 9, kk = i & 511, k = kk & 255;
            float w = Wout[k * 256 + n];
            __nv_bfloat16 h, l; split_bf16(w, h, l);
            g_Bout[i] = (kk < 256) ? h : l;
        }
    } else {
        if (i < 384) g_bcat[i] = (i < 256) ? boff[i] : battn[i - 256];
        int j = i - 384;
        const int PADE = (M_PAD - M_ROWS) * 512;   // 36*512
        if (j >= 0 && j < 3 * PADE) {
            int arr = j / PADE, off = j % PADE;
            __nv_bfloat16 z = __float2bfloat16(0.f);
            __nv_bfloat16* dst = (arr == 0) ? g_Acat1 : (arr == 1) ? g_Acat2 : g_Acat3;
            dst[M_ROWS * 512 + off] = z;
        }
    }
}

// ---------------------------------------------------------------------------
// fp32 [M,256] -> bf16 split [M,512] for inflat (y=0) and query (y=1).
// ---------------------------------------------------------------------------
__global__ void convert_split(const float* __restrict__ inflat,
                              const float* __restrict__ query)
{
    const int e4 = blockIdx.x * blockDim.x + threadIdx.x;
    if (e4 >= M_ROWS * 64) return;
    const float* src = blockIdx.y ? query : inflat;
    __nv_bfloat16* dst = blockIdx.y ? g_Acat2 : g_Acat1;
    const int row = e4 >> 6;
    const int c4  = (e4 & 63) << 2;
    float4 v = *(const float4*)(src + (size_t)row * 256 + c4);
    __nv_bfloat16 h0, l0, h1, l1, h2, l2, h3, l3;
    split_bf16(v.x, h0, l0); split_bf16(v.y, h1, l1);
    split_bf16(v.z, h2, l2); split_bf16(v.w, h3, l3);
    __nv_bfloat162* dh = (__nv_bfloat162*)(dst + (size_t)row * 512 + c4);
    dh[0] = __halves2bfloat162(h0, h1);
    dh[1] = __halves2bfloat162(h2, h3);
    __nv_bfloat162* dl = (__nv_bfloat162*)(dst + (size_t)row * 512 + 256 + c4);
    dl[0] = __halves2bfloat162(l0, l1);
    dl[1] = __halves2bfloat162(l2, l3);
}

// ---------------------------------------------------------------------------
// bf16 split GEMM via mma.sync + cp.async 3-stage pipeline (R8 known-good
// two-barrier loop). One CTA = 128x128 tile, 256 threads = 8 warps (2x4),
// warp tile 64x32. 12 K-chunks of 64 (Ahi*Bhi, Alo*Bhi, Ahi*Blo), fp32 acc.
// 2 CTAs/SM. Dual-problem via split. Optional fp16 output (C16 != null).
// ---------------------------------------------------------------------------
__global__ __launch_bounds__(256, 2)
void gemm_bf16_mma(const __nv_bfloat16* __restrict__ A,
                   const __nv_bfloat16* __restrict__ Bm,
                   const float* __restrict__ bias,
                   float* __restrict__ C, __half* __restrict__ C16,
                   int M, int N, int split,
                   const __nv_bfloat16* __restrict__ A2,
                   const __nv_bfloat16* __restrict__ B2,
                   const float* __restrict__ bias2,
                   float* __restrict__ C2, int N2)
{
    extern __shared__ char dyn[];     // 3 x (16KB A + 16KB B)
    const int tid  = threadIdx.x;
    const int wid  = tid >> 5;
    const int lane = tid & 31;
    const int warp_m = wid & 1;
    const int warp_n = wid >> 1;

    int bx = blockIdx.x;
    if (bx >= split) { A = A2; Bm = B2; bias = bias2; C = C2; C16 = nullptr; N = N2; bx -= split; }
    const int row0 = blockIdx.y * 128;
    const int n0   = bx * 128;

    const uint32_t sbase = smem_u32(dyn);

    float acc[4][4][4];
#pragma unroll
    for (int i = 0; i < 4; i++)
#pragma unroll
        for (int j = 0; j < 4; j++)
#pragma unroll
            for (int k = 0; k < 4; k++) acc[i][j][k] = 0.f;

    const uint4* baseA4 = (const uint4*)(A + (size_t)row0 * 512);
    const uint4* baseB4 = (const uint4*)(Bm + (size_t)n0 * 512);

    const int cr = tid >> 3, ccol = tid & 7;

    auto issue_chunk = [&](int cc) {
        const int s    = cc - (cc / 3) * 3;   // cc % 3
        const int seg  = cc >> 2;
        const int kk   = (cc & 3) * 64;
        const int aoff = (seg == 1) ? 256 : 0;
        const int boff = (seg == 2) ? 256 : 0;
        const uint4* sA = baseA4 + ((aoff + kk) >> 3);
        const uint4* sB = baseB4 + ((boff + kk) >> 3);
        const uint32_t smA = sbase + s * 32768;
        const uint32_t smB = smA + 16384;
#pragma unroll
        for (int i = 0; i < 4; i++) {
            const int r = cr + i * 32;
            const uint32_t off = r * 128 + ccol * 16;
            const uint32_t sw  = off ^ ((off >> 3) & 0x70);
            cp16(smA + sw, sA + (size_t)r * 64 + ccol);
            cp16(smB + sw, sB + (size_t)r * 64 + ccol);
        }
        cp_commit();
    };

    // ldmatrix per-lane constants
    const int t  = lane >> 3;
    const int l7 = lane & 7;
    const uint32_t tlo = (t & 1) * 8;
    const uint32_t tc  = (uint32_t)(t >> 1);
    const uint32_t aRowBase = (warp_m * 64 + tlo + l7) * 128;
    const uint32_t bRowBase = (warp_n * 32 + tlo + l7) * 128;

    auto mma_chunk = [&](int s) {
        const uint32_t baseA = sbase + s * 32768;
        const uint32_t baseB = baseA + 16384;
#pragma unroll
        for (int ks = 0; ks < 4; ks++) {
            const uint32_t csw = (uint32_t)(((ks * 2 + tc) ^ l7) << 4);
            uint32_t bf[2][4];
#pragma unroll
            for (int nt = 0; nt < 2; nt++)
                ldsm4(bf[nt], baseB + bRowBase + nt * (16 * 128) + csw);
#pragma unroll
            for (int mt = 0; mt < 4; mt++) {
                uint32_t af[4];
                ldsm4(af, baseA + aRowBase + mt * (16 * 128) + csw);
                mma16816(acc[mt][0], af, bf[0][0], bf[0][2]);
                mma16816(acc[mt][1], af, bf[0][1], bf[0][3]);
                mma16816(acc[mt][2], af, bf[1][0], bf[1][2]);
                mma16816(acc[mt][3], af, bf[1][1], bf[1][3]);
            }
        }
    };

    // 3-stage pipeline over 12 chunks (two barriers per chunk — known-good)
    issue_chunk(0);
    issue_chunk(1);
    int sidx = 0;
    for (int cc = 0; cc < 12; cc++) {
        if (cc < 11) cp_wait<1>(); else cp_wait<0>();
        __syncthreads();
        mma_chunk(sidx);
        __syncthreads();
        if (cc + 2 < 12) issue_chunk(cc + 2);
        sidx = (sidx == 2) ? 0 : sidx + 1;
    }

    // epilogue: fragment -> global with bias (fp32 or fp16)
#pragma unroll
    for (int mt = 0; mt < 4; mt++) {
        const int m = row0 + warp_m * 64 + mt * 16 + (lane >> 2);
#pragma unroll
        for (int n8 = 0; n8 < 4; n8++) {
            const int c = n0 + warp_n * 32 + n8 * 8 + (lane & 3) * 2;
            const float bx2 = __ldg(&bias[c]);
            const float by2 = __ldg(&bias[c + 1]);
            if (C16) {
                if (m < M)
                    *(__half2*)(C16 + (size_t)m * N + c) =
                        __floats2half2_rn(acc[mt][n8][0] + bx2, acc[mt][n8][1] + by2);
                if (m + 8 < M)
                    *(__half2*)(C16 + (size_t)(m + 8) * N + c) =
                        __floats2half2_rn(acc[mt][n8][2] + bx2, acc[mt][n8][3] + by2);
            } else {
                if (m < M) {
                    float2 o = make_float2(acc[mt][n8][0] + bx2, acc[mt][n8][1] + by2);
                    *(float2*)(C + (size_t)m * N + c) = o;
                }
                if (m + 8 < M) {
                    float2 o = make_float2(acc[mt][n8][2] + bx2, acc[mt][n8][3] + by2);
                    *(float2*)(C + (size_t)(m + 8) * N + c) = o;
                }
            }
        }
    }
}

// ---------------------------------------------------------------------------
// Deformable sampling over fp16 value, select-free hot loop.
// Phase 1: ALL 256 threads; thread = (hd, p, side): side in {x0, x1}. Each
//          computes its side's two corner offsets (y0,y1 rows) + masked
//          weights and writes one int2 + one float2 at [(hd*16+p)*2 + side].
// Phase 2: warp = head; half h of the warp takes side h; lane j = channel
//          pair (2j, 2j+1). Per point: 2 LDS.64 + 2 LDG.32 + 4 F2F + 4 FFMA,
//          no selects. shfl_xor(16) combines sides; hi/lo bf16 out.
// ---------------------------------------------------------------------------
__global__ __launch_bounds__(256)
void msda_sample(const float* __restrict__ refp,   // [B, LQ, 4, 2]
                 const float* __restrict__ proj,   // [M, 384]
                 const __half* __restrict__ value, // [B, LEN_IN, 8, 32] fp16
                 __nv_bfloat16* __restrict__ acat) // [M_PAD, 512]
{
    __shared__ int2   sO2[256];   // [(hd*16+p)*2 + side] -> {oA(y0), oB(y1)}
    __shared__ float2 sW2[256];   // -> {wA, wB}

    const int bq = blockIdx.x;
    const int tt = threadIdx.x;
    const int b  = bq / LQ_;

    {
        const int id   = tt >> 1;        // (hd, p)
        const int side = tt & 1;         // x-corner side
        const int hd   = id >> 4;
        const int p    = id & 15;
        const int lvl  = p >> 2;
        const int pp   = p & 3;

        // softmax over this head's 16 logits; each logit held by 2 adjacent
        // lanes -> xor offsets {2,4,8,16} reduce over all 32 lanes.
        float a = proj[bq * 384 + 256 + hd * 16 + p];
        float m = a;
#pragma unroll
        for (int o = 2; o <= 16; o <<= 1) m = fmaxf(m, __shfl_xor_sync(FULL, m, o));
        float e = __expf(a - m);
        float s = e;
#pragma unroll
        for (int o = 2; o <= 16; o <<= 1) s += __shfl_xor_sync(FULL, s, o);
        const float w = e / s;

        const float wh = c_WH[lvl];
        const int   Wl = c_Wi[lvl];
        const int   Sl = c_S[lvl];
        const float ox = proj[bq * 384 + hd * 32 + lvl * 8 + pp * 2 + 0];
        const float oy = proj[bq * 384 + hd * 32 + lvl * 8 + pp * 2 + 1];
        const float rx = refp[(bq * 4 + lvl) * 2 + 0];
        const float ry = refp[(bq * 4 + lvl) * 2 + 1];

        const float x = fmaf(rx, wh, ox) - 0.5f;
        const float y = fmaf(ry, wh, oy) - 0.5f;

        const float fx0 = floorf(x), fy0 = floorf(y);
        const int   x0  = (int)fx0,  y0  = (int)fy0;
        const float tx_ = x - fx0,   ty_ = y - fy0;

        const int   xs  = x0 + side;                 // this thread's x corner
        const bool  vx  = (xs >= 0) && (xs < Wl);
        const bool  vy0 = (y0 >= 0)     && (y0 < Wl);
        const bool  vy1 = (y0 + 1 >= 0) && (y0 + 1 < Wl);

        const int cx  = min(max(xs, 0),     Wl - 1);
        const int cy0 = min(max(y0, 0),     Wl - 1);
        const int cy1 = min(max(y0 + 1, 0), Wl - 1);

        const float wsx = side ? tx_ : (1.f - tx_);
        const float wA  = (vx && vy0) ? wsx * (1.f - ty_) * w : 0.f;
        const float wB  = (vx && vy1) ? wsx * ty_ * w : 0.f;

        // fp16 element offsets: ((b*LEN_IN + pos)*8 + hd)*32
        const int base = (b * LEN_IN_ + Sl) * 256 + hd * 32;
        int2 ov;
        ov.x = base + (cy0 * Wl + cx) * 256;   // (y0, xs)
        ov.y = base + (cy1 * Wl + cx) * 256;   // (y1, xs)

        sO2[tt] = ov;
        sW2[tt] = make_float2(wA, wB);
    }
    __syncthreads();

    const int hd   = tt >> 5;
    const int lane = tt & 31;
    const int half = lane >> 4;      // side handled by this half-warp
    const int j    = lane & 15;
    const __half* __restrict__ vp = value + 2 * j;
    const int ebase = hd * 32 + half;   // entry (hd*16+p)*2 + half = ebase + 2p

    float accx = 0.f, accy = 0.f;
#pragma unroll
    for (int p = 0; p < 16; p++) {
        const int2   ov = sO2[ebase + 2 * p];
        const float2 wv = sW2[ebase + 2 * p];
        const __half2 hA = *(const __half2*)(vp + ov.x);
        const __half2 hB = *(const __half2*)(vp + ov.y);
        const float2 vA = __half22float2(hA);
        const float2 vB = __half22float2(hB);
        accx = fmaf(wv.x, vA.x, fmaf(wv.y, vB.x, accx));
        accy = fmaf(wv.x, vA.y, fmaf(wv.y, vB.y, accy));
    }

    // combine x0 + x1 sides
    accx += __shfl_xor_sync(FULL, accx, 16);
    accy += __shfl_xor_sync(FULL, accy, 16);

    const __nv_bfloat16 hx = __float2bfloat16(accx);
    const __nv_bfloat16 hy = __float2bfloat16(accy);
    if (half == 0) {
        *(__nv_bfloat162*)(acat + (size_t)bq * 512 + hd * 32 + 2 * j) =
            __halves2bfloat162(hx, hy);
    } else {
        const __nv_bfloat16 lx = __float2bfloat16(accx - __bfloat162float(hx));
        const __nv_bfloat16 ly = __float2bfloat16(accy - __bfloat162float(hy));
        *(__nv_bfloat162*)(acat + (size_t)bq * 512 + 256 + hd * 32 + 2 * j) =
            __halves2bfloat162(lx, ly);
    }
}

// ---------------------------------------------------------------------------
extern "C" void kernel_launch(void* const* d_in, const int* in_sizes, int n_in,
                              void* d_out, int out_size)
{
    const float* query  = (const float*)d_in[0];
    const float* refp   = (const float*)d_in[1];
    const float* inflat = (const float*)d_in[2];
    const float* W_off  = (const float*)d_in[5];
    const float* b_off  = (const float*)d_in[6];
    const float* W_attn = (const float*)d_in[7];
    const float* b_attn = (const float*)d_in[8];
    const float* W_val  = (const float*)d_in[9];
    const float* b_val  = (const float*)d_in[10];
    const float* W_out  = (const float*)d_in[11];
    const float* b_out  = (const float*)d_in[12];
    float* out = (float*)d_out;

    void *pA1, *pA2, *pA3, *pBval, *pBqkv, *pBout, *pbcat, *pv16, *pproj;
    cudaGetSymbolAddress(&pA1, g_Acat1);
    cudaGetSymbolAddress(&pA2, g_Acat2);
    cudaGetSymbolAddress(&pA3, g_Acat3);
    cudaGetSymbolAddress(&pBval, g_Bval);
    cudaGetSymbolAddress(&pBqkv, g_Bqkv);
    cudaGetSymbolAddress(&pBout, g_Bout);
    cudaGetSymbolAddress(&pbcat, g_bcat);
    cudaGetSymbolAddress(&pv16, g_value16);
    cudaGetSymbolAddress(&pproj, g_proj);

    const int DSMEM = 3 * 32768;   // 96KB
    cudaFuncSetAttribute(gemm_bf16_mma,
                         cudaFuncAttributeMaxDynamicSharedMemorySize, DSMEM);

    pack_misc<<<dim3(768, 4), 256>>>(W_off, b_off, W_attn, b_attn, W_val, W_out);

    convert_split<<<dim3((M_ROWS * 64 + 255) / 256, 2), 256>>>(inflat, query);

    // fused launch: x<2 -> value GEMM (fp16 out), x>=2 -> proj GEMM (fp32 out)
    gemm_bf16_mma<<<dim3(5, MT_), 256, DSMEM>>>(
        (const __nv_bfloat16*)pA1, (const __nv_bfloat16*)pBval,
        b_val, nullptr, (__half*)pv16, M_ROWS, 256, 2,
        (const __nv_bfloat16*)pA2, (const __nv_bfloat16*)pBqkv,
        (const float*)pbcat, (float*)pproj, 384);

    msda_sample<<<M_ROWS, 256>>>(refp, (const float*)pproj,
                                 (const __half*)pv16, (__nv_bfloat16*)pA3);

    gemm_bf16_mma<<<dim3(2, MT_), 256, DSMEM>>>(
        (const __nv_bfloat16*)pA3, (const __nv_bfloat16*)pBout,
        b_out, out, nullptr, M_ROWS, 256, 2,
        (const __nv_bfloat16*)pA3, (const __nv_bfloat16*)pBout,
        b_out, out, 256);
}